// round 11
// baseline (speedup 1.0000x reference)
#include <cuda_runtime.h>
#include <cuda_bf16.h>
#include <math.h>

// ---------------- scratch (no cudaMalloc allowed) ----------------
__device__ __align__(16) float g_h1[4096];     // after in_W0
__device__ __align__(16) float g_h2[4096];     // after in_W1
__device__ __align__(16) float g_params[2112]; // after in_W2
__device__ __align__(16) float g_cpg[64];      // cpg_out
__device__ __align__(16) float g_h3[2048];     // after out_W0
__device__ __align__(16) float g_h4[2048];     // after out_W1

// grid barrier: per-block flag slots (128B apart, no atomic contention) +
// master-scan release. Phase/flags are monotonic -> graph-replay-safe.
__device__ volatile unsigned g_phase = 0;
__device__ unsigned g_flags[256 * 32];         // slot b at g_flags[b*32]

// ---------------- reductions ----------------
__device__ __forceinline__ float warp_reduce(float v) {
#pragma unroll
    for (int o = 16; o; o >>= 1) v += __shfl_down_sync(0xffffffffu, v, o);
    return v;
}

// ---------------- grid-wide barrier (all blocks resident) ----------------
// Arrival = one volatile store to the block's own slot (parallel, no LTS
// serialization). Warp 0 of block 0 scans all flags (5 loads/lane/sweep),
// then bumps the phase; everyone else polls the phase line (plain reads).
__device__ __forceinline__ void grid_barrier() {
    __syncthreads();
    if (threadIdx.x < 32) {
        const unsigned p = g_phase;            // stable between barriers
        if (threadIdx.x == 0) {
            __threadfence();                   // release this block's writes
            *(volatile unsigned*)&g_flags[blockIdx.x * 32] = p + 1;
        }
        if (blockIdx.x == 0) {
            bool done = false;
            while (!done) {
                done = true;
                for (unsigned i = threadIdx.x; i < gridDim.x; i += 32)
                    if (*(volatile unsigned*)&g_flags[i * 32] < p + 1) done = false;
                done = __all_sync(0xffffffffu, done);
            }
            __threadfence();
            if (threadIdx.x == 0) g_phase = p + 1;
        } else if (threadIdx.x == 0) {
            while (g_phase < p + 1) {}
        }
        __threadfence();                       // acquire
    }
    __syncthreads();
}

// ---------------- accurate sin: fp32 Cody-Waite 3-term + quadrant ----------
// Immune to --use_fast_math (hand-rolled). DP fallback for |x|>32768 (unused
// in practice). qoff=1 gives cos.
__device__ __forceinline__ float trig_acc(float x, int qoff) {
    float q, r;
    if (__builtin_expect(fabsf(x) > 32768.0f, 0)) {
        double xd = (double)x;
        double qd = rint(xd * 0.63661977236758138);
        q = (float)qd;
        r = (float)fma(qd, -1.5707963267948966, xd);
    } else {
        q = rintf(x * 0.63661977236758138f);
        r = fmaf(q, -1.5703125f, x);
        r = fmaf(q, -4.837512969970703125e-4f, r);
        r = fmaf(q, -7.549789948768648e-8f, r);
    }
    int n = ((int)q + qoff) & 3;
    float r2 = r * r;
    float ps = fmaf(r2, fmaf(r2, -1.9515295891e-4f, 8.3321608736e-3f), -1.6666654611e-1f);
    float s  = fmaf(r * r2, ps, r);
    float pc = fmaf(r2, fmaf(r2, -1.388731625493765e-3f, 4.166664568298827e-2f),
                    -4.999999905424326e-1f);
    float c  = fmaf(r2, pc, 1.0f);
    float v  = (n & 1) ? c : s;
    return (n & 2) ? -v : v;
}
__device__ __forceinline__ float sin_acc(float x) { return trig_acc(x, 0); }
__device__ __forceinline__ float cos_acc(float x) { return trig_acc(x, 1); }

// ---------------- L2 prefetch helper ----------------
__device__ __forceinline__ void l2_prefetch_region(const char* p, size_t bytes,
                                                   unsigned gid, unsigned gthreads) {
    size_t lines = bytes >> 7;
    for (size_t l = gid; l < lines; l += gthreads)
        asm volatile("prefetch.global.L2 [%0];" :: "l"(p + (l << 7)));
}

// named barrier over threads 0..255 (warps 0-7) of the block
#define BAR256() asm volatile("bar.sync 1, 256;" ::: "memory")

// ---------------- CPG RK4(3/8), threads 0..255 of one block --------------
// i = tid&31 (oscillator), g = tid>>5 (8 groups x 4 coupling partners).
// ODE (reference slot permutation replicated exactly):
//   s0' = s1
//   s1' = ifr[i] + sum_j s0[i]*cw[i][j]*sin(s2[j]-s2[i]-pb[i][j])
//   s2' = 1000*(250*(ia[i]-s0[i]) - s1[i])
// Output: a = new[0:32], ph = new[32:64]; cpg_out = [a*cos(ph), a*sin(ph)]
__device__ void cpg_compute_nb(const float* params, const float* state,
                               const float* t_ptr, float* out_state, float* cpg_out) {
    const int tid = threadIdx.x;  // 0..255
    const int i   = tid & 31;
    const int g   = tid >> 5;     // 0..7

    __shared__ float sh_ph[2][32];
    __shared__ float sh_part[8][32];

    float cwv[4], pbv[4];
#pragma unroll
    for (int k = 0; k < 4; k++) {
        cwv[k] = __ldcg(params + 64 + 32 * i + 4 * g + k);
        pbv[k] = __ldcg(params + 64 + 1024 + 32 * i + 4 * g + k);
    }
    const float ia  = __ldcg(params + i);
    const float ifr = __ldcg(params + 32 + i);
    const float h   = *t_ptr;
    const float s0 = state[i], s1 = state[32 + i], s2 = state[64 + i];

    int stage = 0;
    auto f = [&](float a0, float a1, float a2, float& d0, float& d1, float& d2) {
        int buf = stage & 1;
        if (g == 0) sh_ph[buf][i] = a2;
        BAR256();
        const float* ph = sh_ph[buf] + 4 * g;
        float acc0, acc1;
        acc0 = cwv[0] * sin_acc(ph[0] - a2 - pbv[0]);
        acc1 = cwv[1] * sin_acc(ph[1] - a2 - pbv[1]);
        acc0 = fmaf(cwv[2], sin_acc(ph[2] - a2 - pbv[2]), acc0);
        acc1 = fmaf(cwv[3], sin_acc(ph[3] - a2 - pbv[3]), acc1);
        sh_part[g][i] = acc0 + acc1;
        BAR256();
        float coup = ((sh_part[0][i] + sh_part[1][i]) + (sh_part[2][i] + sh_part[3][i]))
                   + ((sh_part[4][i] + sh_part[5][i]) + (sh_part[6][i] + sh_part[7][i]));
        d1 = fmaf(a0, coup, ifr);
        d0 = a1;
        d2 = 1000.0f * fmaf(250.0f, ia - a0, -a1);
        stage++;
    };

    float k10, k11, k12, k20, k21, k22, k30, k31, k32, k40, k41, k42;
    f(s0, s1, s2, k10, k11, k12);
    f(s0 + h * k10 / 3.0f, s1 + h * k11 / 3.0f, s2 + h * k12 / 3.0f, k20, k21, k22);
    f(s0 + h * (k20 - k10 / 3.0f), s1 + h * (k21 - k11 / 3.0f), s2 + h * (k22 - k12 / 3.0f),
      k30, k31, k32);
    f(s0 + h * (k10 - k20 + k30), s1 + h * (k11 - k21 + k31), s2 + h * (k12 - k22 + k32),
      k40, k41, k42);

    float n0 = s0 + h * 0.125f * (k10 + 3.0f * (k20 + k30) + k40);
    float n1 = s1 + h * 0.125f * (k11 + 3.0f * (k21 + k31) + k41);
    float n2 = s2 + h * 0.125f * (k12 + 3.0f * (k22 + k32) + k42);

    if (g == 0) {
        out_state[i]      = n0;
        out_state[32 + i] = n1;
        out_state[64 + i] = n2;
        // a = n0, ph = n1 (reference reads ph from slot [n:2n])
        cpg_out[i]      = n0 * cos_acc(n1);
        cpg_out[32 + i] = n0 * sin_acc(n1);
    }
}

// ---------------- the whole network: one persistent kernel ----------------
// gridDim.x = #SMs (all blocks resident). Warp-per-row GEMVs; cheap grid
// barriers between layers. Block 0 runs the CPG step; others prefetch.
__global__ void __launch_bounds__(1024, 1)
cpg_net(const float* __restrict__ state, const float* __restrict__ x,
        const float* __restrict__ t,
        const float* __restrict__ inW0, const float* __restrict__ inb0,
        const float* __restrict__ inW1, const float* __restrict__ inb1,
        const float* __restrict__ inW2, const float* __restrict__ inb2,
        const float* __restrict__ outW0, const float* __restrict__ outb0,
        const float* __restrict__ outW1, const float* __restrict__ outb1,
        const float* __restrict__ outW2, const float* __restrict__ outb2,
        float* __restrict__ out) {
    const int tid   = threadIdx.x;
    const int lane  = tid & 31;
    const int wid   = tid >> 5;
    const int gw0   = blockIdx.x * 32 + wid;       // global warp id
    const int gstep = gridDim.x * 32;              // warps in grid

    float* h1 = g_h1; float* h2 = g_h2; float* params = g_params;
    float* cpg = g_cpg; float* h3 = g_h3; float* h4 = g_h4;

    // ---- L0: h1 = relu(inW0 @ [x, t]), 4096 rows x 2049 (scalar loads) ----
    for (int row = gw0; row < 4096; row += gstep) {
        const float* Wr = inW0 + (size_t)row * 2049;
        float s = 0.0f;
#pragma unroll 8
        for (int k = 0; k < 64; k++) {
            int j = lane + 32 * k;
            s = fmaf(__ldcs(Wr + j), x[j], s);
        }
        if (lane == 0) s = fmaf(__ldcs(Wr + 2048), *t, s);
        s = warp_reduce(s);
        if (lane == 0) h1[row] = fmaxf(s + inb0[row], 0.0f);
    }
    grid_barrier();

    // ---- L1: h2 = relu(inW1 @ h1), 4096 rows x 4096 ----
    for (int row = gw0; row < 4096; row += gstep) {
        const float4* Wr = (const float4*)(inW1 + (size_t)row * 4096);
        const float4* xv = (const float4*)h1;
        float s = 0.0f;
#pragma unroll 8
        for (int k = 0; k < 32; k++) {
            int j = lane + 32 * k;
            float4 w = __ldcs(Wr + j);
            float4 v = xv[j];
            s += w.x * v.x + w.y * v.y + w.z * v.z + w.w * v.w;
        }
        s = warp_reduce(s);
        if (lane == 0) h2[row] = fmaxf(s + inb1[row], 0.0f);
    }
    grid_barrier();

    // ---- L2: params = inW2 @ h2, 2112 rows x 4096 (no relu) ----
    for (int row = gw0; row < 2112; row += gstep) {
        const float4* Wr = (const float4*)(inW2 + (size_t)row * 4096);
        const float4* xv = (const float4*)h2;
        float s = 0.0f;
#pragma unroll 8
        for (int k = 0; k < 32; k++) {
            int j = lane + 32 * k;
            float4 w = __ldcs(Wr + j);
            float4 v = xv[j];
            s += w.x * v.x + w.y * v.y + w.z * v.z + w.w * v.w;
        }
        s = warp_reduce(s);
        if (lane == 0) params[row] = s + inb2[row];
    }
    grid_barrier();

    // ---- L3: CPG RK4 step (block 0, threads 0-255); others prefetch ----
    if (blockIdx.x == 0) {
        if (tid < 256) cpg_compute_nb(params, state, t, out, cpg);
    } else {
        unsigned gid = (blockIdx.x - 1) * 1024u + tid;
        unsigned gth = (gridDim.x - 1) * 1024u;
        l2_prefetch_region((const char*)outW0, 2048u * 64u * 4u, gid, gth);
        l2_prefetch_region((const char*)outW1, 2048u * 2048u * 4u, gid, gth);
        l2_prefetch_region((const char*)outW2, 1024u * 2048u * 4u, gid, gth);
    }
    grid_barrier();

    // ---- L4: h3 = relu(outW0 @ cpg), 2048 rows x 64 ----
    for (int row = gw0; row < 2048; row += gstep) {
        const float* Wr = outW0 + (size_t)row * 64;
        float s = fmaf(Wr[lane], cpg[lane], Wr[32 + lane] * cpg[32 + lane]);
        s = warp_reduce(s);
        if (lane == 0) h3[row] = fmaxf(s + outb0[row], 0.0f);
    }
    grid_barrier();

    // ---- L5: h4 = relu(outW1 @ h3), 2048 rows x 2048 ----
    for (int row = gw0; row < 2048; row += gstep) {
        const float4* Wr = (const float4*)(outW1 + (size_t)row * 2048);
        const float4* xv = (const float4*)h3;
        float s = 0.0f;
#pragma unroll 8
        for (int k = 0; k < 16; k++) {
            int j = lane + 32 * k;
            float4 w = Wr[j];
            float4 v = xv[j];
            s += w.x * v.x + w.y * v.y + w.z * v.z + w.w * v.w;
        }
        s = warp_reduce(s);
        if (lane == 0) h4[row] = fmaxf(s + outb1[row], 0.0f);
    }
    grid_barrier();

    // ---- L6: out[96:] = outW2 @ h4, 1024 rows x 2048 (no relu) ----
    for (int row = gw0; row < 1024; row += gstep) {
        const float4* Wr = (const float4*)(outW2 + (size_t)row * 2048);
        const float4* xv = (const float4*)h4;
        float s = 0.0f;
#pragma unroll 8
        for (int k = 0; k < 16; k++) {
            int j = lane + 32 * k;
            float4 w = Wr[j];
            float4 v = xv[j];
            s += w.x * v.x + w.y * v.y + w.z * v.z + w.w * v.w;
        }
        s = warp_reduce(s);
        if (lane == 0) out[96 + row] = s + outb2[row];
    }
}

// ---------------- host ----------------
extern "C" void kernel_launch(void* const* d_in, const int* in_sizes, int n_in,
                              void* d_out, int out_size) {
    const float* state = (const float*)d_in[0];
    const float* x     = (const float*)d_in[1];
    const float* t     = (const float*)d_in[2];
    const float* inW0  = (const float*)d_in[3];
    const float* inb0  = (const float*)d_in[4];
    const float* inW1  = (const float*)d_in[5];
    const float* inb1  = (const float*)d_in[6];
    const float* inW2  = (const float*)d_in[7];
    const float* inb2  = (const float*)d_in[8];
    const float* outW0 = (const float*)d_in[9];
    const float* outb0 = (const float*)d_in[10];
    const float* outW1 = (const float*)d_in[11];
    const float* outb1 = (const float*)d_in[12];
    const float* outW2 = (const float*)d_in[13];
    const float* outb2 = (const float*)d_in[14];
    float* out = (float*)d_out;

    int dev = 0, sms = 148;
    cudaGetDevice(&dev);
    cudaDeviceGetAttribute(&sms, cudaDevAttrMultiProcessorCount, dev);
    if (sms < 1) sms = 148;
    if (sms > 256) sms = 256;  // flag-array capacity

    cpg_net<<<sms, 1024>>>(state, x, t,
                           inW0, inb0, inW1, inb1, inW2, inb2,
                           outW0, outb0, outW1, outb1, outW2, outb2,
                           out);
}

// round 12
// speedup vs baseline: 1.3829x; 1.3829x over previous
#include <cuda_runtime.h>
#include <cuda_bf16.h>
#include <math.h>

// ---------------- scratch (no cudaMalloc allowed) ----------------
__device__ __align__(16) float g_h1[4096];     // after in_W0
__device__ __align__(16) float g_h2[4096];     // after in_W1
__device__ __align__(16) float g_params[2112]; // after in_W2
__device__ __align__(16) float g_cpg[64];      // cpg_out
__device__ __align__(16) float g_h3[2048];     // after out_W0
__device__ __align__(16) float g_h4[2048];     // after out_W1
__device__ unsigned g_done = 0;                // last-block counter (self-resetting)

// ---------------- reductions ----------------
__device__ __forceinline__ float warp_reduce(float v) {
#pragma unroll
    for (int o = 16; o; o >>= 1) v += __shfl_down_sync(0xffffffffu, v, o);
    return v;
}

// ---------------- accurate sin: fp32 Cody-Waite 3-term + quadrant ----------
// Immune to --use_fast_math (hand-rolled). DP fallback for |x|>32768 (unused
// in practice). qoff=1 gives cos.
__device__ __forceinline__ float trig_acc(float x, int qoff) {
    float q, r;
    if (__builtin_expect(fabsf(x) > 32768.0f, 0)) {
        double xd = (double)x;
        double qd = rint(xd * 0.63661977236758138);
        q = (float)qd;
        r = (float)fma(qd, -1.5707963267948966, xd);
    } else {
        q = rintf(x * 0.63661977236758138f);
        r = fmaf(q, -1.5703125f, x);
        r = fmaf(q, -4.837512969970703125e-4f, r);
        r = fmaf(q, -7.549789948768648e-8f, r);
    }
    int n = ((int)q + qoff) & 3;
    float r2 = r * r;
    float ps = fmaf(r2, fmaf(r2, -1.9515295891e-4f, 8.3321608736e-3f), -1.6666654611e-1f);
    float s  = fmaf(r * r2, ps, r);
    float pc = fmaf(r2, fmaf(r2, -1.388731625493765e-3f, 4.166664568298827e-2f),
                    -4.999999905424326e-1f);
    float c  = fmaf(r2, pc, 1.0f);
    float v  = (n & 1) ? c : s;
    return (n & 2) ? -v : v;
}
__device__ __forceinline__ float sin_acc(float x) { return trig_acc(x, 0); }
__device__ __forceinline__ float cos_acc(float x) { return trig_acc(x, 1); }

// ---------------- L2 prefetch helper ----------------
__device__ __forceinline__ void l2_prefetch_region(const char* p, size_t bytes,
                                                   unsigned gid, unsigned gthreads) {
    size_t lines = bytes >> 7;
    for (size_t l = gid; l < lines; l += gthreads)
        asm volatile("prefetch.global.L2 [%0];" :: "l"(p + (l << 7)));
}

// ---------------- CPG RK4(3/8) device function (256 threads) ----------------
// i = tid&31 (oscillator), g = tid>>5 (8 groups x 4 coupling partners).
// ODE (reference slot permutation replicated exactly):
//   s0' = s1
//   s1' = ifr[i] + sum_j s0[i]*cw[i][j]*sin(s2[j]-s2[i]-pb[i][j])
//   s2' = 1000*(250*(ia[i]-s0[i]) - s1[i])
// Output: a = new[0:32], ph = new[32:64]; cpg_out = [a*cos(ph), a*sin(ph)]
__device__ void cpg_compute(const float* params, const float* state,
                            const float* t_ptr, float* out_state, float* cpg_out) {
    const int tid = threadIdx.x;  // 0..255
    const int i   = tid & 31;
    const int g   = tid >> 5;     // 0..7

    __shared__ float sh_ph[2][32];
    __shared__ float sh_part[8][32];

    float cwv[4], pbv[4];
#pragma unroll
    for (int k = 0; k < 4; k++) {
        cwv[k] = __ldcg(params + 64 + 32 * i + 4 * g + k);
        pbv[k] = __ldcg(params + 64 + 1024 + 32 * i + 4 * g + k);
    }
    const float ia  = __ldcg(params + i);
    const float ifr = __ldcg(params + 32 + i);
    const float h   = *t_ptr;
    const float s0 = state[i], s1 = state[32 + i], s2 = state[64 + i];

    int stage = 0;
    auto f = [&](float a0, float a1, float a2, float& d0, float& d1, float& d2) {
        int buf = stage & 1;
        if (g == 0) sh_ph[buf][i] = a2;
        __syncthreads();
        const float* ph = sh_ph[buf] + 4 * g;
        float acc0, acc1;
        acc0 = cwv[0] * sin_acc(ph[0] - a2 - pbv[0]);
        acc1 = cwv[1] * sin_acc(ph[1] - a2 - pbv[1]);
        acc0 = fmaf(cwv[2], sin_acc(ph[2] - a2 - pbv[2]), acc0);
        acc1 = fmaf(cwv[3], sin_acc(ph[3] - a2 - pbv[3]), acc1);
        sh_part[g][i] = acc0 + acc1;
        __syncthreads();
        float coup = ((sh_part[0][i] + sh_part[1][i]) + (sh_part[2][i] + sh_part[3][i]))
                   + ((sh_part[4][i] + sh_part[5][i]) + (sh_part[6][i] + sh_part[7][i]));
        d1 = fmaf(a0, coup, ifr);
        d0 = a1;
        d2 = 1000.0f * fmaf(250.0f, ia - a0, -a1);
        stage++;
    };

    float k10, k11, k12, k20, k21, k22, k30, k31, k32, k40, k41, k42;
    f(s0, s1, s2, k10, k11, k12);
    f(s0 + h * k10 / 3.0f, s1 + h * k11 / 3.0f, s2 + h * k12 / 3.0f, k20, k21, k22);
    f(s0 + h * (k20 - k10 / 3.0f), s1 + h * (k21 - k11 / 3.0f), s2 + h * (k22 - k12 / 3.0f),
      k30, k31, k32);
    f(s0 + h * (k10 - k20 + k30), s1 + h * (k11 - k21 + k31), s2 + h * (k12 - k22 + k32),
      k40, k41, k42);

    float n0 = s0 + h * 0.125f * (k10 + 3.0f * (k20 + k30) + k40);
    float n1 = s1 + h * 0.125f * (k11 + 3.0f * (k21 + k31) + k41);
    float n2 = s2 + h * 0.125f * (k12 + 3.0f * (k22 + k32) + k42);

    if (g == 0) {
        out_state[i]      = n0;
        out_state[32 + i] = n1;
        out_state[64 + i] = n2;
        // a = n0, ph = n1 (reference reads ph from slot [n:2n])
        cpg_out[i]      = n0 * cos_acc(n1);
        cpg_out[32 + i] = n0 * sin_acc(n1);
    }
}

// ---------------- GEMV kernels (4 rows/block) ----------------
// Layer 0: rows=4096, cols=2049 (last col multiplies timestep). Scalar loads
// (row stride 2049 breaks float4 alignment on odd rows); 4 rows/block.
// Tail: prefetch next layer's weights into L2 using idle DRAM cycles.
__global__ void gemv_in0(const float* __restrict__ W, const float* __restrict__ b,
                         const float* __restrict__ x, const float* __restrict__ t,
                         float* __restrict__ y,
                         const char* pf, size_t pf_bytes) {
    int r0 = blockIdx.x * 4;
    const float* W0 = W + (size_t)r0 * 2049;
    const float* W1 = W0 + 2049;
    const float* W2 = W1 + 2049;
    const float* W3 = W2 + 2049;
    float s0 = 0.0f, s1 = 0.0f, s2 = 0.0f, s3 = 0.0f;
#pragma unroll
    for (int it = 0; it < 8; it++) {
        int j = threadIdx.x + it * 256;
        float xv = x[j];
        s0 = fmaf(__ldcs(W0 + j), xv, s0);
        s1 = fmaf(__ldcs(W1 + j), xv, s1);
        s2 = fmaf(__ldcs(W2 + j), xv, s2);
        s3 = fmaf(__ldcs(W3 + j), xv, s3);
    }
    if (threadIdx.x == 0) {
        float tv = *t;
        s0 = fmaf(__ldcs(W0 + 2048), tv, s0);
        s1 = fmaf(__ldcs(W1 + 2048), tv, s1);
        s2 = fmaf(__ldcs(W2 + 2048), tv, s2);
        s3 = fmaf(__ldcs(W3 + 2048), tv, s3);
    }
    __shared__ float sm[4][8];
    int lane = threadIdx.x & 31, w = threadIdx.x >> 5;
    s0 = warp_reduce(s0); s1 = warp_reduce(s1);
    s2 = warp_reduce(s2); s3 = warp_reduce(s3);
    if (lane == 0) { sm[0][w] = s0; sm[1][w] = s1; sm[2][w] = s2; sm[3][w] = s3; }
    __syncthreads();
    if (w == 0) {
        int rr = lane >> 3, sl = lane & 7;
        float v = sm[rr][sl];
        v += __shfl_down_sync(0xffffffffu, v, 4);
        v += __shfl_down_sync(0xffffffffu, v, 2);
        v += __shfl_down_sync(0xffffffffu, v, 1);
        if (sl == 0) y[r0 + rr] = fmaxf(v + b[r0 + rr], 0.0f);
    }
    if (pf) {
        unsigned gid = blockIdx.x * 256u + threadIdx.x;
        unsigned gth = gridDim.x * 256u;
        l2_prefetch_region(pf, pf_bytes, gid, gth);
    }
}

// float4 GEMV, 4 rows per 256-thread block, COLS % 1024 == 0.
// FUSE_CPG: after all blocks finish, the last block runs the CPG step inline
// while the other blocks prefetch the output-MLP weights into L2.
// tail_pf (non-FUSE path): prefetch next layer's weights into L2.
template<int COLS, bool RELU, bool FUSE_CPG>
__global__ void gemv4(const float* __restrict__ W, const float* __restrict__ b,
                      const float* __restrict__ x, float* __restrict__ y,
                      const float* state, const float* t,
                      float* out_state, float* cpg_out,
                      const float* pf0, const float* pf1, const float* pf2,
                      const char* tail_pf, size_t tail_pf_bytes) {
    constexpr int N4 = COLS / 4;
    constexpr int ITERS = N4 / 256;
    int r0 = blockIdx.x * 4;
    const float4* W0 = (const float4*)(W + (size_t)r0 * COLS);
    const float4* W1 = (const float4*)(W + (size_t)(r0 + 1) * COLS);
    const float4* W2 = (const float4*)(W + (size_t)(r0 + 2) * COLS);
    const float4* W3 = (const float4*)(W + (size_t)(r0 + 3) * COLS);
    const float4* x4 = (const float4*)x;
    float s0 = 0.0f, s1 = 0.0f, s2 = 0.0f, s3 = 0.0f;
#pragma unroll
    for (int it = 0; it < ITERS; it++) {
        int j = threadIdx.x + it * 256;
        float4 v  = x4[j];
        float4 w0 = __ldcs(W0 + j);
        float4 w1 = __ldcs(W1 + j);
        float4 w2 = __ldcs(W2 + j);
        float4 w3 = __ldcs(W3 + j);
        s0 += w0.x * v.x + w0.y * v.y + w0.z * v.z + w0.w * v.w;
        s1 += w1.x * v.x + w1.y * v.y + w1.z * v.z + w1.w * v.w;
        s2 += w2.x * v.x + w2.y * v.y + w2.z * v.z + w2.w * v.w;
        s3 += w3.x * v.x + w3.y * v.y + w3.z * v.z + w3.w * v.w;
    }
    __shared__ float sm[4][8];
    int lane = threadIdx.x & 31, w = threadIdx.x >> 5;
    s0 = warp_reduce(s0); s1 = warp_reduce(s1);
    s2 = warp_reduce(s2); s3 = warp_reduce(s3);
    if (lane == 0) { sm[0][w] = s0; sm[1][w] = s1; sm[2][w] = s2; sm[3][w] = s3; }
    __syncthreads();
    if (w == 0) {
        int rr = lane >> 3, sl = lane & 7;
        float v = sm[rr][sl];
        v += __shfl_down_sync(0xffffffffu, v, 4);
        v += __shfl_down_sync(0xffffffffu, v, 2);
        v += __shfl_down_sync(0xffffffffu, v, 1);
        if (sl == 0) {
            float r = v + b[r0 + rr];
            y[r0 + rr] = RELU ? fmaxf(r, 0.0f) : r;
        }
    }

    if (FUSE_CPG) {
        // last-block election: writers fence, then RMW on a shared counter
        __shared__ unsigned sh_last;
        __threadfence();
        __syncthreads();
        if (threadIdx.x == 0)
            sh_last = (atomicAdd(&g_done, 1u) == gridDim.x - 1u) ? 1u : 0u;
        __syncthreads();
        if (sh_last) {
            if (threadIdx.x == 0) g_done = 0; // reset for next graph replay
            cpg_compute(y, state, t, out_state, cpg_out);
        } else {
            // prefetch the output MLP's weights into L2 during the cpg stall
            unsigned gid = blockIdx.x * 256u + threadIdx.x;
            unsigned gth = gridDim.x * 256u;
            l2_prefetch_region((const char*)pf0, 2048u * 64u * 4u, gid, gth);
            l2_prefetch_region((const char*)pf1, 2048u * 2048u * 4u, gid, gth);
            l2_prefetch_region((const char*)pf2, 1024u * 2048u * 4u, gid, gth);
        }
    } else if (tail_pf) {
        unsigned gid = blockIdx.x * 256u + threadIdx.x;
        unsigned gth = gridDim.x * 256u;
        l2_prefetch_region(tail_pf, tail_pf_bytes, gid, gth);
    }
}

// Small GEMV (cols = 64): 2 rows per warp, 8 warps/block.
__global__ void gemv_w64(const float* __restrict__ W, const float* __restrict__ b,
                         const float* __restrict__ x, float* __restrict__ y) {
    int warp_id = (blockIdx.x * blockDim.x + threadIdx.x) >> 5;
    int lane = threadIdx.x & 31;
    int r0 = warp_id * 2;
    const float* W0 = W + (size_t)r0 * 64;
    const float* W1 = W0 + 64;
    float x0 = x[lane], x1 = x[32 + lane];
    float s0 = fmaf(W0[lane], x0, W0[32 + lane] * x1);
    float s1 = fmaf(W1[lane], x0, W1[32 + lane] * x1);
    s0 = warp_reduce(s0);
    s1 = warp_reduce(s1);
    if (lane == 0) {
        y[r0]     = fmaxf(s0 + b[r0], 0.0f);
        y[r0 + 1] = fmaxf(s1 + b[r0 + 1], 0.0f);
    }
}

// ---------------- host ----------------
extern "C" void kernel_launch(void* const* d_in, const int* in_sizes, int n_in,
                              void* d_out, int out_size) {
    const float* state = (const float*)d_in[0];
    const float* x     = (const float*)d_in[1];
    const float* t     = (const float*)d_in[2];
    const float* inW0  = (const float*)d_in[3];
    const float* inb0  = (const float*)d_in[4];
    const float* inW1  = (const float*)d_in[5];
    const float* inb1  = (const float*)d_in[6];
    const float* inW2  = (const float*)d_in[7];
    const float* inb2  = (const float*)d_in[8];
    const float* outW0 = (const float*)d_in[9];
    const float* outb0 = (const float*)d_in[10];
    const float* outW1 = (const float*)d_in[11];
    const float* outb1 = (const float*)d_in[12];
    const float* outW2 = (const float*)d_in[13];
    const float* outb2 = (const float*)d_in[14];
    float* out = (float*)d_out;

    float *h1, *h2, *params, *cpg, *h3, *h4;
    cudaGetSymbolAddress((void**)&h1, g_h1);
    cudaGetSymbolAddress((void**)&h2, g_h2);
    cudaGetSymbolAddress((void**)&params, g_params);
    cudaGetSymbolAddress((void**)&cpg, g_cpg);
    cudaGetSymbolAddress((void**)&h3, g_h3);
    cudaGetSymbolAddress((void**)&h4, g_h4);

    // input MLP; each kernel tail-prefetches the NEXT layer's weights into L2
    gemv_in0<<<1024, 256>>>(inW0, inb0, x, t, h1,
                            (const char*)inW1, 4096ull * 4096ull * 4ull);
    gemv4<4096, true, false><<<1024, 256>>>(inW1, inb1, h1, h2,
                                            nullptr, nullptr, nullptr, nullptr,
                                            nullptr, nullptr, nullptr,
                                            (const char*)inW2, 2112ull * 4096ull * 4ull);
    gemv4<4096, false, true><<<528, 256>>>(inW2, inb2, h2, params,
                                           state, t, out, cpg,
                                           outW0, outW1, outW2,
                                           nullptr, 0);

    // output MLP
    gemv_w64<<<128, 256>>>(outW0, outb0, cpg, h3);
    gemv4<2048, true, false><<<512, 256>>>(outW1, outb1, h3, h4,
                                           nullptr, nullptr, nullptr, nullptr,
                                           nullptr, nullptr, nullptr,
                                           nullptr, 0);
    gemv4<2048, false, false><<<256, 256>>>(outW2, outb2, h4, out + 96,
                                            nullptr, nullptr, nullptr, nullptr,
                                            nullptr, nullptr, nullptr,
                                            nullptr, 0);
}